// round 1
// baseline (speedup 1.0000x reference)
#include <cuda_runtime.h>
#include <math.h>

// Problem constants (shapes fixed by the dataset)
#define B 8
#define N 1024
#define C 256
#define K 256          // k_max = ceil(0.25 * 1024)
#define C2 512         // Wqkv second dim
#define SCALE 0.17677669529663687f   // (C/H)^-0.5 = 1/sqrt(32)

// Output layout: [new_X (8*256*256) | new_adj (8*256*256) | new_mask (8*256)]
#define OUT_ADJ_OFF  (B*K*C)          // 524288
#define OUT_MASK_OFF (2*B*K*C)        // 1048576

// ---- scratch (no allocations allowed) ----
__device__ float d_part[B*8*C];       // partial column sums of X
__device__ float d_u[B*C];            // score projection vector per batch
__device__ float d_scores[B*N];       // masked scores
__device__ int   d_idxg[B*K];         // top-k indices (sorted desc by score)
__device__ float d_gate[B*K];         // tanh(val)*new_mask
__device__ float d_nm[B*K];           // new_mask

// ---------------------------------------------------------------------------
// K1: partial column sums of X.  grid (8 chunks, 8 batches), 256 threads.
// Thread c sums X[b, chunk*128 .. +128, c] (fully coalesced).
// ---------------------------------------------------------------------------
__global__ void k_partial(const float* __restrict__ X) {
    int b = blockIdx.y, ch = blockIdx.x, c = threadIdx.x;
    const float* xp = X + ((size_t)b * N + (size_t)ch * 128) * C + c;
    float s = 0.f;
    #pragma unroll 8
    for (int r = 0; r < 128; r++) s += xp[(size_t)r * C];
    d_part[(b * 8 + ch) * C + c] = s;
}

// ---------------------------------------------------------------------------
// K2: finish Xsum, then two tiny 256x256 matvecs:
//   ksum = Xsum @ Wk ;  u = Wq @ ksum.   grid (8), 256 threads.
// ---------------------------------------------------------------------------
__global__ void k_uvec(const float* __restrict__ Wqkv) {
    int b = blockIdx.x, t = threadIdx.x;
    __shared__ float xs[C];
    __shared__ float ks[C];
    float s = 0.f;
    #pragma unroll
    for (int ch = 0; ch < 8; ch++) s += d_part[(b * 8 + ch) * C + t];
    xs[t] = s;
    __syncthreads();
    // ksum[t] = sum_c Xsum[c] * Wqkv[c, 256 + t]   (coalesced across t)
    float ka = 0.f;
    for (int c = 0; c < C; c++) ka += xs[c] * Wqkv[(size_t)c * C2 + C + t];
    ks[t] = ka;
    __syncthreads();
    // u[t] = sum_j Wqkv[t, j] * ksum[j]            (row-contiguous per thread)
    const float* wrow = Wqkv + (size_t)t * C2;
    float ua = 0.f;
    for (int j = 0; j < C; j++) ua += wrow[j] * ks[j];
    d_u[b * C + t] = ua;
}

// ---------------------------------------------------------------------------
// K3: scores[b,n] = mask ? SCALE * X[b,n,:] . u[b] : -1e9
// grid (128, 8), 256 threads (8 warps, 1 row per warp). float4 loads.
// ---------------------------------------------------------------------------
__global__ void k_scores(const float* __restrict__ X,
                         const float* __restrict__ mask) {
    int b = blockIdx.y, t = threadIdx.x;
    __shared__ float us[C];
    us[t] = d_u[b * C + t];
    __syncthreads();
    int warp = t >> 5, lane = t & 31;
    int n = blockIdx.x * 8 + warp;
    const float4* xr = (const float4*)(X + ((size_t)b * N + n) * C);
    const float4* ur = (const float4*)us;
    float acc = 0.f;
    #pragma unroll
    for (int it = 0; it < 2; it++) {
        float4 xv = xr[lane + it * 32];
        float4 uv = ur[lane + it * 32];
        acc += xv.x * uv.x + xv.y * uv.y + xv.z * uv.z + xv.w * uv.w;
    }
    #pragma unroll
    for (int o = 16; o; o >>= 1) acc += __shfl_xor_sync(0xffffffffu, acc, o);
    if (lane == 0) {
        float m = mask[b * N + n];
        d_scores[b * N + n] = (m > 0.f) ? SCALE * acc : -1e9f;
    }
}

// ---------------------------------------------------------------------------
// K4: per-batch full bitonic sort of 1024 (score, idx) keys, take top 256.
// Key = (~orderedFloat(score) << 32) | idx  -> ascending sort == desc score,
// ascending index tie-break (matches jax.lax.top_k). grid (8), 512 threads.
// ---------------------------------------------------------------------------
__global__ void k_topk(const float* __restrict__ mask,
                       float* __restrict__ out /* d_out base */) {
    int b = blockIdx.x, t = threadIdx.x;
    __shared__ unsigned long long sk[N];
    __shared__ float red[16];
    __shared__ int s_ki;

    for (int i = t; i < N; i += 512) {
        float f = d_scores[b * N + i];
        unsigned u = __float_as_uint(f);
        u = (u & 0x80000000u) ? ~u : (u | 0x80000000u);   // order-preserving
        sk[i] = ((unsigned long long)(~u) << 32) | (unsigned)i;
    }
    // mask sum -> k_i
    float ms = 0.f;
    for (int i = t; i < N; i += 512) ms += mask[b * N + i];
    #pragma unroll
    for (int o = 16; o; o >>= 1) ms += __shfl_xor_sync(0xffffffffu, ms, o);
    if ((t & 31) == 0) red[t >> 5] = ms;
    __syncthreads();
    if (t == 0) {
        float s = 0.f;
        for (int w = 0; w < 16; w++) s += red[w];
        s_ki = (int)ceilf(0.25f * s);
    }
    // bitonic ascending sort of 1024 u64 keys
    for (unsigned k = 2; k <= N; k <<= 1) {
        for (unsigned j = k >> 1; j > 0; j >>= 1) {
            __syncthreads();
            for (unsigned i = t; i < N; i += 512) {
                unsigned l = i ^ j;
                if (l > i) {
                    unsigned long long a = sk[i], bb = sk[l];
                    bool up = ((i & k) == 0);
                    if ((a > bb) == up) { sk[i] = bb; sk[l] = a; }
                }
            }
        }
    }
    __syncthreads();
    if (t < K) {
        unsigned long long key = sk[t];
        int n = (int)(unsigned)key;
        float val = d_scores[b * N + n];
        float nm = (t < s_ki) ? 1.f : 0.f;
        d_idxg[b * K + t] = n;
        d_gate[b * K + t] = tanhf(val) * nm;
        d_nm[b * K + t]   = nm;
        out[OUT_MASK_OFF + b * K + t] = nm;
    }
}

// ---------------------------------------------------------------------------
// K5: new_X[b,i,:] = X[b, idx[b,i], :] * gate[b,i].
// grid (256, 8), 64 threads, float4.
// ---------------------------------------------------------------------------
__global__ void k_gatherx(const float* __restrict__ X, float* __restrict__ out) {
    int b = blockIdx.y, i = blockIdx.x, t = threadIdx.x;
    int r = d_idxg[b * K + i];
    float g = d_gate[b * K + i];
    const float4* src = (const float4*)(X + ((size_t)b * N + r) * C);
    float4* dst = (float4*)(out + ((size_t)b * K + i) * C);
    float4 v = src[t];
    dst[t] = make_float4(v.x * g, v.y * g, v.z * g, v.w * g);
}

// ---------------------------------------------------------------------------
// K6: new_adj[b,i,j] = adj[b, idx[i], idx[j]] * nm[i] * nm[j].
// grid (256, 8), 256 threads. Scattered 4B reads within a 4KB row.
// ---------------------------------------------------------------------------
__global__ void k_gatheradj(const float* __restrict__ adj, float* __restrict__ out) {
    int b = blockIdx.y, i = blockIdx.x, t = threadIdx.x;
    __shared__ int   sidx[K];
    __shared__ float snm[K];
    sidx[t] = d_idxg[b * K + t];
    snm[t]  = d_nm[b * K + t];
    __syncthreads();
    int ri = sidx[i];
    float nmi = snm[i];
    const float* row = adj + (size_t)b * N * N + (size_t)ri * N;
    out[OUT_ADJ_OFF + ((size_t)b * K + i) * K + t] = row[sidx[t]] * nmi * snm[t];
}

// ---------------------------------------------------------------------------
extern "C" void kernel_launch(void* const* d_in, const int* in_sizes, int n_in,
                              void* d_out, int out_size) {
    const float* X    = (const float*)d_in[0];
    const float* adj  = (const float*)d_in[1];
    const float* mask = (const float*)d_in[2];
    const float* Wqkv = (const float*)d_in[3];
    float* out = (float*)d_out;

    k_partial<<<dim3(8, B), 256>>>(X);
    k_uvec<<<B, 256>>>(Wqkv);
    k_scores<<<dim3(N / 8, B), 256>>>(X, mask);
    k_topk<<<B, 512>>>(mask, out);
    k_gatherx<<<dim3(K, B), 64>>>(X, out);
    k_gatheradj<<<dim3(K, B), 256>>>(adj, out);
}

// round 2
// speedup vs baseline: 1.1809x; 1.1809x over previous
#include <cuda_runtime.h>
#include <math.h>

// Problem constants (shapes fixed by the dataset)
#define B 8
#define N 1024
#define C 256
#define K 256          // k_max = ceil(0.25 * 1024)
#define C2 512         // Wqkv second dim
#define SCALE 0.17677669529663687f   // (C/H)^-0.5 = 1/sqrt(32)

// Output layout: [new_X (8*256*256) | new_adj (8*256*256) | new_mask (8*256)]
#define OUT_ADJ_OFF  (B*K*C)
#define OUT_MASK_OFF (2*B*K*C)

#define NCHUNK 64      // partial-sum chunks per batch (16 rows each)

// ---- scratch (no allocations allowed) ----
__device__ float d_part[B*NCHUNK*C];
__device__ float d_u[B*C];
__device__ float d_scores[B*N];
__device__ int   d_idxg[B*K];
__device__ float d_gate[B*K];
__device__ float d_nm[B*K];

// ---------------------------------------------------------------------------
// K1: partial column sums of X. grid (64 chunks, 8 batches), 256 threads.
// Thread c sums X[b, chunk*16 .. +16, c] (fully coalesced, 512 blocks wide).
// ---------------------------------------------------------------------------
__global__ void k_partial(const float* __restrict__ X) {
    int b = blockIdx.y, ch = blockIdx.x, c = threadIdx.x;
    const float* xp = X + ((size_t)b * N + (size_t)ch * 16) * C + c;
    float s = 0.f;
    #pragma unroll
    for (int r = 0; r < 16; r++) s += xp[(size_t)r * C];
    d_part[(b * NCHUNK + ch) * C + c] = s;
}

// ---------------------------------------------------------------------------
// K2: finish Xsum, then two tiny 256x256 matvecs:
//   ksum = Xsum @ Wk ;  u = Wq @ ksum.   grid (8), 256 threads.
// ---------------------------------------------------------------------------
__global__ void k_uvec(const float* __restrict__ Wqkv) {
    int b = blockIdx.x, t = threadIdx.x;
    __shared__ float xs[C];
    __shared__ float ks[C];
    float s = 0.f;
    #pragma unroll
    for (int ch = 0; ch < NCHUNK; ch++) s += d_part[(b * NCHUNK + ch) * C + t];
    xs[t] = s;
    __syncthreads();
    float ka = 0.f;
    for (int c = 0; c < C; c++) ka += xs[c] * Wqkv[(size_t)c * C2 + C + t];
    ks[t] = ka;
    __syncthreads();
    const float* wrow = Wqkv + (size_t)t * C2;
    float ua = 0.f;
    for (int j = 0; j < C; j++) ua += wrow[j] * ks[j];
    d_u[b * C + t] = ua;
}

// ---------------------------------------------------------------------------
// K3: scores[b,n] = mask ? SCALE * X[b,n,:] . u[b] : -1e9
// grid (128, 8), 256 threads (8 warps, 1 row per warp), float4 loads.
// ---------------------------------------------------------------------------
__global__ void k_scores(const float* __restrict__ X,
                         const float* __restrict__ mask) {
    int b = blockIdx.y, t = threadIdx.x;
    __shared__ float us[C];
    us[t] = d_u[b * C + t];
    __syncthreads();
    int warp = t >> 5, lane = t & 31;
    int n = blockIdx.x * 8 + warp;
    const float4* xr = (const float4*)(X + ((size_t)b * N + n) * C);
    const float4* ur = (const float4*)us;
    float acc = 0.f;
    #pragma unroll
    for (int it = 0; it < 2; it++) {
        float4 xv = xr[lane + it * 32];
        float4 uv = ur[lane + it * 32];
        acc += xv.x * uv.x + xv.y * uv.y + xv.z * uv.z + xv.w * uv.w;
    }
    #pragma unroll
    for (int o = 16; o; o >>= 1) acc += __shfl_xor_sync(0xffffffffu, acc, o);
    if (lane == 0) {
        float m = mask[b * N + n];
        d_scores[b * N + n] = (m > 0.f) ? SCALE * acc : -1e9f;
    }
}

// ---------------------------------------------------------------------------
// K4: per-batch hybrid bitonic sort of 1024 keys. 1024 threads, 1 key/thread.
// Key = (~orderedFloat(score) << 32) | idx ; ascending sort == desc score,
// ascending index tie-break (matches jax.lax.top_k).
// j>=32 stages via shared memory; j<=16 stages via warp shuffle (no barrier).
// ---------------------------------------------------------------------------
__global__ void __launch_bounds__(1024, 1)
k_topk(const float* __restrict__ mask, float* __restrict__ out) {
    int b = blockIdx.x, t = threadIdx.x;
    __shared__ unsigned long long sk[N];
    __shared__ float red[32];
    __shared__ int s_ki;

    // build own key
    float f = d_scores[b * N + t];
    unsigned u = __float_as_uint(f);
    u = (u & 0x80000000u) ? ~u : (u | 0x80000000u);
    unsigned long long v = ((unsigned long long)(~u) << 32) | (unsigned)t;

    // mask sum -> k_i (32-warp reduction)
    float ms = mask[b * N + t];
    #pragma unroll
    for (int o = 16; o; o >>= 1) ms += __shfl_xor_sync(0xffffffffu, ms, o);
    if ((t & 31) == 0) red[t >> 5] = ms;
    __syncthreads();
    if (t == 0) {
        float s = 0.f;
        #pragma unroll
        for (int w = 0; w < 32; w++) s += red[w];
        s_ki = (int)ceilf(0.25f * s);
    }

    // bitonic sort, ascending over full 1024
    #pragma unroll
    for (unsigned k = 2; k <= 1024; k <<= 1) {
        bool dir_up = ((t & k) == 0);
        // shared-memory stages (partner outside warp)
        for (unsigned j = k >> 1; j >= 32; j >>= 1) {
            sk[t] = v;
            __syncthreads();
            unsigned long long w = sk[t ^ j];
            bool lower = ((t & j) == 0);
            bool takeMin = (lower == dir_up);
            v = takeMin ? (v < w ? v : w) : (v > w ? v : w);
            __syncthreads();
        }
        // in-warp stages
        unsigned jstart = (k >> 1) < 16u ? (k >> 1) : 16u;
        for (unsigned j = jstart; j >= 1; j >>= 1) {
            unsigned long long w = __shfl_xor_sync(0xffffffffu, v, j);
            bool lower = ((t & j) == 0);
            bool takeMin = (lower == dir_up);
            v = takeMin ? (v < w ? v : w) : (v > w ? v : w);
        }
    }

    // publish sorted keys, emit top-K
    sk[t] = v;
    __syncthreads();
    if (t < K) {
        unsigned long long key = sk[t];
        int n = (int)(unsigned)key;
        // recover score from key (inverse of the order-preserving transform)
        unsigned uh = ~(unsigned)(key >> 32);
        unsigned orig = (uh & 0x80000000u) ? (uh & 0x7fffffffu) : ~uh;
        float val = __uint_as_float(orig);
        float nm = (t < s_ki) ? 1.f : 0.f;
        d_idxg[b * K + t] = n;
        d_gate[b * K + t] = tanhf(val) * nm;
        d_nm[b * K + t]   = nm;
        out[OUT_MASK_OFF + b * K + t] = nm;
    }
}

// ---------------------------------------------------------------------------
// K5: merged gathers. grid (256, 8), 256 threads.
//   new_X[b,i,:]  = X[b, idx[b,i], :] * gate[b,i]
//   new_adj[b,i,j]= adj[b, idx[i], idx[j]] * nm[i] * nm[j]
// ---------------------------------------------------------------------------
__global__ void k_gather(const float* __restrict__ X,
                         const float* __restrict__ adj,
                         float* __restrict__ out) {
    int b = blockIdx.y, i = blockIdx.x, t = threadIdx.x;
    __shared__ int   sidx[K];
    __shared__ float snm[K];
    sidx[t] = d_idxg[b * K + t];
    snm[t]  = d_nm[b * K + t];
    __syncthreads();
    int ri = sidx[i];
    float nmi = snm[i];
    float g = d_gate[b * K + i];
    // new_X row (coalesced)
    out[((size_t)b * K + i) * C + t] = X[((size_t)b * N + ri) * C + t] * g;
    // new_adj row (scattered reads within one 4KB adj row)
    const float* row = adj + (size_t)b * N * N + (size_t)ri * N;
    out[OUT_ADJ_OFF + ((size_t)b * K + i) * K + t] = row[sidx[t]] * nmi * snm[t];
}

// ---------------------------------------------------------------------------
extern "C" void kernel_launch(void* const* d_in, const int* in_sizes, int n_in,
                              void* d_out, int out_size) {
    const float* X    = (const float*)d_in[0];
    const float* adj  = (const float*)d_in[1];
    const float* mask = (const float*)d_in[2];
    const float* Wqkv = (const float*)d_in[3];
    float* out = (float*)d_out;

    k_partial<<<dim3(NCHUNK, B), 256>>>(X);
    k_uvec<<<B, 256>>>(Wqkv);
    k_scores<<<dim3(N / 8, B), 256>>>(X, mask);
    k_topk<<<B, 1024>>>(mask, out);
    k_gather<<<dim3(K, B), 256>>>(X, adj, out);
}